// round 1
// baseline (speedup 1.0000x reference)
#include <cuda_runtime.h>
#include <cuda_bf16.h>
#include <cstdint>

// ---------------- scratch (static __device__ -- no allocation) ----------------
// tokens = 256*256 = 65536
__device__ float g_mu[65536];
__device__ float g_rstd[65536];
// A[(i*32+c)*256 + s], B[(j*32+e)*256 + s]   (8192 x 256 each)
__device__ float g_A[8192 * 256];
__device__ float g_B[8192 * 256];
// G2[((i*256+j))*1024 + c*32 + e]  = 268 MB
__device__ float g_G[67108864];
// norm[i*256+j]
__device__ float g_norm[65536];

#define EPS_MASK 1e-3f
#define LN_EPS   1e-5f

// ------------------------------- K0: LN stats ---------------------------------
// one warp per token; 8 tokens per 256-thread block
__global__ void k0_stats(const float* __restrict__ m) {
    int token = blockIdx.x * 8 + (threadIdx.x >> 5);
    int lane  = threadIdx.x & 31;
    const float4* p = (const float4*)(m + (size_t)token * 256);
    float4 v1 = p[lane];
    float4 v2 = p[lane + 32];
    float s  = v1.x + v1.y + v1.z + v1.w + v2.x + v2.y + v2.z + v2.w;
    float sq = v1.x*v1.x + v1.y*v1.y + v1.z*v1.z + v1.w*v1.w
             + v2.x*v2.x + v2.y*v2.y + v2.z*v2.z + v2.w*v2.w;
    #pragma unroll
    for (int o = 16; o; o >>= 1) {
        s  += __shfl_xor_sync(0xFFFFFFFFu, s,  o);
        sq += __shfl_xor_sync(0xFFFFFFFFu, sq, o);
    }
    if (lane == 0) {
        float mu  = s * (1.0f / 256.0f);
        float var = sq * (1.0f / 256.0f) - mu * mu;
        g_mu[token]   = mu;
        g_rstd[token] = rsqrtf(var + LN_EPS);
    }
}

// ------------------------------ Knorm: mask gram ------------------------------
__global__ void k_norm(const float* __restrict__ mask) {
    int i = blockIdx.x, j = threadIdx.x;
    float acc = EPS_MASK;
    for (int s = 0; s < 256; s++)
        acc += mask[s * 256 + i] * mask[s * 256 + j];
    g_norm[i * 256 + j] = acc;
}

// ------------------- K1: LN + dual projection, transposed out ------------------
// grid (256 [n], 8 [s-tile of 32]), block 256
__global__ __launch_bounds__(256) void k1_proj(
    const float* __restrict__ m, const float* __restrict__ mask,
    const float* __restrict__ lnw, const float* __restrict__ lnb,
    const float* __restrict__ w1, const float* __restrict__ b1,
    const float* __restrict__ w2, const float* __restrict__ b2)
{
    __shared__ float ln[32][257];
    __shared__ float outs[64][33];
    __shared__ float slnw[256], slnb[256];

    const int t  = threadIdx.x;
    const int n  = blockIdx.x;
    const int s0 = blockIdx.y * 32;

    slnw[t] = lnw[t];
    slnb[t] = lnb[t];
    __syncthreads();

    // load + layernorm 32 tokens x 256 dims
    #pragma unroll
    for (int it = 0; it < 8; it++) {
        int row = (t >> 6) + it * 4;      // 0..31
        int col = (t & 63) * 4;           // 0..252
        int s   = s0 + row;
        float4 v = *(const float4*)(m + ((size_t)s * 256 + n) * 256 + col);
        float mu = g_mu[s * 256 + n];
        float rs = g_rstd[s * 256 + n];
        ln[row][col + 0] = (v.x - mu) * rs * slnw[col + 0] + slnb[col + 0];
        ln[row][col + 1] = (v.y - mu) * rs * slnw[col + 1] + slnb[col + 1];
        ln[row][col + 2] = (v.z - mu) * rs * slnw[col + 2] + slnb[col + 2];
        ln[row][col + 3] = (v.w - mu) * rs * slnw[col + 3] + slnb[col + 3];
    }
    __syncthreads();

    // project: thread -> output channel c64 (0..31 => w1/A, 32..63 => w2/B),
    // 8 s-values {sg, sg+4, ..., sg+28}
    const int c64 = t & 63;
    const int sg  = t >> 6;
    const float* wp;
    float bias;
    if (c64 < 32) { wp = w1 + c64;        bias = b1[c64];      }
    else          { wp = w2 + (c64 - 32); bias = b2[c64 - 32]; }

    float acc[8];
    #pragma unroll
    for (int q = 0; q < 8; q++) acc[q] = 0.0f;

    for (int k = 0; k < 256; k++) {
        float wv = wp[(size_t)k * 32];
        #pragma unroll
        for (int q = 0; q < 8; q++)
            acc[q] += ln[sg + q * 4][k] * wv;
    }

    #pragma unroll
    for (int q = 0; q < 8; q++) {
        int sl = sg + q * 4;
        float mval = mask[(size_t)(s0 + sl) * 256 + n];
        outs[c64][sl] = (acc[q] + bias) * mval;
    }
    __syncthreads();

    // coalesced transposed store
    #pragma unroll
    for (int rep = 0; rep < 2; rep++) {
        int idx  = t + rep * 256;         // 0..511
        int row  = idx >> 3;              // 0..63
        int col4 = (idx & 7) * 4;         // 0..28
        float4 v = make_float4(outs[row][col4 + 0], outs[row][col4 + 1],
                               outs[row][col4 + 2], outs[row][col4 + 3]);
        float* buf = (row < 32) ? g_A : g_B;
        int cc = row & 31;
        *(float4*)(buf + ((size_t)n * 32 + cc) * 256 + s0 + col4) = v;
    }
}

// ----------------------- K2: G = A * B^T  (8192x8192x256) ---------------------
// 128x128 tile, 256 threads, 8x8 microtile (strided 4+4), permuted store to G2
__global__ __launch_bounds__(256, 2) void k2_outer() {
    __shared__ float As[8][132];
    __shared__ float Bs[8][132];

    const int t  = threadIdx.x;
    const int bi = blockIdx.y;
    const int bj = blockIdx.x;

    const int lrow = t >> 1;
    const int lk4  = (t & 1) * 4;
    const int tx   = t & 15;
    const int ty   = t >> 4;

    const float* Ap = g_A + (size_t)bi * 128 * 256 + (size_t)lrow * 256 + lk4;
    const float* Bp = g_B + (size_t)bj * 128 * 256 + (size_t)lrow * 256 + lk4;

    float acc[8][8];
    #pragma unroll
    for (int i = 0; i < 8; i++)
        #pragma unroll
        for (int j = 0; j < 8; j++) acc[i][j] = 0.0f;

    float4 av = *(const float4*)Ap;
    float4 bv = *(const float4*)Bp;

    for (int kt = 0; kt < 256; kt += 8) {
        __syncthreads();
        As[lk4 + 0][lrow] = av.x; As[lk4 + 1][lrow] = av.y;
        As[lk4 + 2][lrow] = av.z; As[lk4 + 3][lrow] = av.w;
        Bs[lk4 + 0][lrow] = bv.x; Bs[lk4 + 1][lrow] = bv.y;
        Bs[lk4 + 2][lrow] = bv.z; Bs[lk4 + 3][lrow] = bv.w;
        __syncthreads();
        if (kt + 8 < 256) {
            av = *(const float4*)(Ap + kt + 8);
            bv = *(const float4*)(Bp + kt + 8);
        }
        #pragma unroll
        for (int kk = 0; kk < 8; kk++) {
            float ar[8], br[8];
            *(float4*)(ar)     = *(const float4*)(&As[kk][ty * 4]);
            *(float4*)(ar + 4) = *(const float4*)(&As[kk][ty * 4 + 64]);
            *(float4*)(br)     = *(const float4*)(&Bs[kk][tx * 4]);
            *(float4*)(br + 4) = *(const float4*)(&Bs[kk][tx * 4 + 64]);
            #pragma unroll
            for (int i = 0; i < 8; i++)
                #pragma unroll
                for (int j = 0; j < 8; j++)
                    acc[i][j] += ar[i] * br[j];
        }
    }

    // permuted store: rI=(i*32+c), cJ=(j*32+e) -> G2[(i*256+j)*1024 + c*32 + e]
    #pragma unroll
    for (int ih = 0; ih < 2; ih++) {
        #pragma unroll
        for (int i4 = 0; i4 < 4; i4++) {
            int ii = ih * 4 + i4;
            int rI = bi * 128 + ty * 4 + i4 + ih * 64;
            int i  = rI >> 5;
            int c  = rI & 31;
            size_t rbase = ((size_t)i << 18) + ((size_t)c << 5);
            #pragma unroll
            for (int jh = 0; jh < 2; jh++) {
                int cJ = bj * 128 + tx * 4 + jh * 64;
                int j  = cJ >> 5;
                int e  = cJ & 31;
                float4 v = make_float4(acc[ii][jh * 4 + 0], acc[ii][jh * 4 + 1],
                                       acc[ii][jh * 4 + 2], acc[ii][jh * 4 + 3]);
                *(float4*)(g_G + rbase + ((size_t)j << 10) + e) = v;
            }
        }
    }
}

// ------------- K3: out = (G2 @ w_out + b_out) / norm (65536x128x1024) ----------
__global__ __launch_bounds__(256, 2) void k3_final(
    const float* __restrict__ w_out, const float* __restrict__ b_out,
    float* __restrict__ dout)
{
    __shared__ float As[8][132];
    __shared__ float Bs[8][132];

    const int t  = threadIdx.x;
    const int bm = blockIdx.x;          // m-tile; N=128 covered by one tile

    const int lrow = t >> 1;
    const int lk4  = (t & 1) * 4;
    const int tx   = t & 15;
    const int ty   = t >> 4;

    const float* Ap = g_G + (size_t)bm * 128 * 1024 + (size_t)lrow * 1024 + lk4;
    const int wk = t >> 5;              // 0..7
    const int z4 = (t & 31) * 4;        // 0..124
    const float* Wp = w_out + (size_t)wk * 128 + z4;

    float acc[8][8];
    #pragma unroll
    for (int i = 0; i < 8; i++)
        #pragma unroll
        for (int j = 0; j < 8; j++) acc[i][j] = 0.0f;

    float4 av = *(const float4*)Ap;
    float4 wv = *(const float4*)Wp;

    for (int kt = 0; kt < 1024; kt += 8) {
        __syncthreads();
        As[lk4 + 0][lrow] = av.x; As[lk4 + 1][lrow] = av.y;
        As[lk4 + 2][lrow] = av.z; As[lk4 + 3][lrow] = av.w;
        *(float4*)(&Bs[wk][z4]) = wv;
        __syncthreads();
        if (kt + 8 < 1024) {
            av = *(const float4*)(Ap + kt + 8);
            wv = *(const float4*)(Wp + (size_t)(kt + 8) * 128);
        }
        #pragma unroll
        for (int kk = 0; kk < 8; kk++) {
            float ar[8], br[8];
            *(float4*)(ar)     = *(const float4*)(&As[kk][ty * 4]);
            *(float4*)(ar + 4) = *(const float4*)(&As[kk][ty * 4 + 64]);
            *(float4*)(br)     = *(const float4*)(&Bs[kk][tx * 4]);
            *(float4*)(br + 4) = *(const float4*)(&Bs[kk][tx * 4 + 64]);
            #pragma unroll
            for (int i = 0; i < 8; i++)
                #pragma unroll
                for (int j = 0; j < 8; j++)
                    acc[i][j] += ar[i] * br[j];
        }
    }

    #pragma unroll
    for (int ih = 0; ih < 2; ih++) {
        #pragma unroll
        for (int i4 = 0; i4 < 4; i4++) {
            int ii  = ih * 4 + i4;
            int row = bm * 128 + ty * 4 + i4 + ih * 64;
            float inv = 1.0f / g_norm[row];
            #pragma unroll
            for (int jh = 0; jh < 2; jh++) {
                int col = tx * 4 + jh * 64;
                float4 bo = *(const float4*)(b_out + col);
                float4 v;
                v.x = (acc[ii][jh * 4 + 0] + bo.x) * inv;
                v.y = (acc[ii][jh * 4 + 1] + bo.y) * inv;
                v.z = (acc[ii][jh * 4 + 2] + bo.z) * inv;
                v.w = (acc[ii][jh * 4 + 3] + bo.w) * inv;
                *(float4*)(dout + (size_t)row * 128 + col) = v;
            }
        }
    }
}

// ----------------------------------- launch -----------------------------------
extern "C" void kernel_launch(void* const* d_in, const int* in_sizes, int n_in,
                              void* d_out, int out_size)
{
    const float* m     = (const float*)d_in[0];
    const float* mask  = (const float*)d_in[1];
    const float* ln_w  = (const float*)d_in[2];
    const float* ln_b  = (const float*)d_in[3];
    const float* w1    = (const float*)d_in[4];
    const float* b1    = (const float*)d_in[5];
    const float* w2    = (const float*)d_in[6];
    const float* b2    = (const float*)d_in[7];
    const float* w_out = (const float*)d_in[8];
    const float* b_out = (const float*)d_in[9];
    float* out = (float*)d_out;

    k0_stats<<<8192, 256>>>(m);
    k_norm<<<256, 256>>>(mask);
    k1_proj<<<dim3(256, 8), 256>>>(m, mask, ln_w, ln_b, w1, b1, w2, b2);
    k2_outer<<<dim3(64, 64), 256>>>();
    k3_final<<<512, 256>>>(w_out, b_out, out);
}

// round 3
// speedup vs baseline: 2.1053x; 2.1053x over previous
#include <cuda_runtime.h>
#include <cuda_bf16.h>
#include <cstdint>

// ---------------- scratch (static __device__ -- no allocation) ----------------
__device__ float g_mu[65536];
__device__ float g_rstd[65536];
__device__ float g_A[8192 * 256];      // A[(i*32+c)][s]  tf32-rounded
__device__ float g_B[8192 * 256];      // B[(j*32+e)][s]  tf32-rounded
__device__ float g_G[67108864];        // G2[(i*256+j)*1024 + c*32 + e] tf32-rounded
__device__ float g_norm[65536];
__device__ float g_Wt[128 * 1024];     // Wt[z][k] = tf32(w_out[k][z])

#define EPS_MASK 1e-3f
#define LN_EPS   1e-5f

// ------------------------------ helpers ---------------------------------------
__device__ __forceinline__ uint32_t smem_u32(const void* p) {
    uint32_t a;
    asm("{ .reg .u64 t; cvta.to.shared.u64 t, %1; cvt.u32.u64 %0, t; }"
        : "=r"(a) : "l"(p));
    return a;
}
__device__ __forceinline__ float tf32_rn(float x) {
    uint32_t u;
    asm("cvt.rn.tf32.f32 %0, %1;" : "=r"(u) : "f"(x));
    return __uint_as_float(u);
}
__device__ __forceinline__ void cp16(uint32_t saddr, const void* gaddr) {
    asm volatile("cp.async.cg.shared.global [%0], [%1], 16;"
                 :: "r"(saddr), "l"(gaddr) : "memory");
}
#define CP_COMMIT() asm volatile("cp.async.commit_group;" ::: "memory")
#define CP_WAIT0()  asm volatile("cp.async.wait_group 0;" ::: "memory")
#define CP_WAIT1()  asm volatile("cp.async.wait_group 1;" ::: "memory")

__device__ __forceinline__ void mma_tf32(float* d, const uint32_t* a, const uint32_t* b) {
    asm volatile(
        "mma.sync.aligned.m16n8k8.row.col.f32.tf32.tf32.f32 "
        "{%0,%1,%2,%3}, {%4,%5,%6,%7}, {%8,%9}, {%0,%1,%2,%3};"
        : "+f"(d[0]), "+f"(d[1]), "+f"(d[2]), "+f"(d[3])
        : "r"(a[0]), "r"(a[1]), "r"(a[2]), "r"(a[3]), "r"(b[0]), "r"(b[1]));
}

// smem tile geometry: 128 rows x 32 k, pitch 36 floats (conflict-free frags)
#define PITCH 36
#define TILE_FLOATS (128 * PITCH)           // 4608
#define GEMM_SMEM_BYTES (4 * TILE_FLOATS * 4)  // A[2] + B[2] = 73728 B

// ------------------------------- K0: LN stats ---------------------------------
__global__ void k0_stats(const float* __restrict__ m) {
    int token = blockIdx.x * 8 + (threadIdx.x >> 5);
    int lane  = threadIdx.x & 31;
    const float4* p = (const float4*)(m + (size_t)token * 256);
    float4 v1 = p[lane];
    float4 v2 = p[lane + 32];
    float s  = v1.x + v1.y + v1.z + v1.w + v2.x + v2.y + v2.z + v2.w;
    float sq = v1.x*v1.x + v1.y*v1.y + v1.z*v1.z + v1.w*v1.w
             + v2.x*v2.x + v2.y*v2.y + v2.z*v2.z + v2.w*v2.w;
    #pragma unroll
    for (int o = 16; o; o >>= 1) {
        s  += __shfl_xor_sync(0xFFFFFFFFu, s,  o);
        sq += __shfl_xor_sync(0xFFFFFFFFu, sq, o);
    }
    if (lane == 0) {
        float mu  = s * (1.0f / 256.0f);
        float var = sq * (1.0f / 256.0f) - mu * mu;
        g_mu[token]   = mu;
        g_rstd[token] = rsqrtf(var + LN_EPS);
    }
}

// ------------------------------ Knorm: mask gram ------------------------------
__global__ void k_norm(const float* __restrict__ mask) {
    int i = blockIdx.x, j = threadIdx.x;
    float acc = EPS_MASK;
    for (int s = 0; s < 256; s++)
        acc += mask[s * 256 + i] * mask[s * 256 + j];
    g_norm[i * 256 + j] = acc;
}

// -------------------- Kwt: tiled transpose + tf32 round of w_out ---------------
// w_out[k][z] (1024 x 128) -> g_Wt[z][k] (128 x 1024)
__global__ void k_wt(const float* __restrict__ w_out) {
    __shared__ float tile[32][33];
    int kt = blockIdx.x * 32;
    int zt = blockIdx.y * 32;
    int tx = threadIdx.x & 31, ty = threadIdx.x >> 5;   // 256 thr: ty 0..7
    #pragma unroll
    for (int r = 0; r < 32; r += 8)
        tile[ty + r][tx] = w_out[(size_t)(kt + ty + r) * 128 + zt + tx];
    __syncthreads();
    #pragma unroll
    for (int r = 0; r < 32; r += 8)
        g_Wt[(size_t)(zt + ty + r) * 1024 + kt + tx] = tf32_rn(tile[tx][ty + r]);
}

// ------------------- K1: LN + dual projection, transposed out ------------------
__global__ __launch_bounds__(256) void k1_proj(
    const float* __restrict__ m, const float* __restrict__ mask,
    const float* __restrict__ lnw, const float* __restrict__ lnb,
    const float* __restrict__ w1, const float* __restrict__ b1,
    const float* __restrict__ w2, const float* __restrict__ b2)
{
    __shared__ float ln[32][257];
    __shared__ float outs[64][33];
    __shared__ float slnw[256], slnb[256];

    const int t  = threadIdx.x;
    const int n  = blockIdx.x;
    const int s0 = blockIdx.y * 32;

    slnw[t] = lnw[t];
    slnb[t] = lnb[t];
    __syncthreads();

    #pragma unroll
    for (int it = 0; it < 8; it++) {
        int row = (t >> 6) + it * 4;
        int col = (t & 63) * 4;
        int s   = s0 + row;
        float4 v = *(const float4*)(m + ((size_t)s * 256 + n) * 256 + col);
        float mu = g_mu[s * 256 + n];
        float rs = g_rstd[s * 256 + n];
        ln[row][col + 0] = (v.x - mu) * rs * slnw[col + 0] + slnb[col + 0];
        ln[row][col + 1] = (v.y - mu) * rs * slnw[col + 1] + slnb[col + 1];
        ln[row][col + 2] = (v.z - mu) * rs * slnw[col + 2] + slnb[col + 2];
        ln[row][col + 3] = (v.w - mu) * rs * slnw[col + 3] + slnb[col + 3];
    }
    __syncthreads();

    const int c64 = t & 63;
    const int sg  = t >> 6;
    const float* wp;
    float bias;
    if (c64 < 32) { wp = w1 + c64;        bias = b1[c64];      }
    else          { wp = w2 + (c64 - 32); bias = b2[c64 - 32]; }

    float acc[8];
    #pragma unroll
    for (int q = 0; q < 8; q++) acc[q] = 0.0f;

    for (int k = 0; k < 256; k++) {
        float wv = wp[(size_t)k * 32];
        #pragma unroll
        for (int q = 0; q < 8; q++)
            acc[q] += ln[sg + q * 4][k] * wv;
    }

    #pragma unroll
    for (int q = 0; q < 8; q++) {
        int sl = sg + q * 4;
        float mval = mask[(size_t)(s0 + sl) * 256 + n];
        outs[c64][sl] = (acc[q] + bias) * mval;
    }
    __syncthreads();

    #pragma unroll
    for (int rep = 0; rep < 2; rep++) {
        int idx  = t + rep * 256;
        int row  = idx >> 3;
        int col4 = (idx & 7) * 4;
        float4 v = make_float4(tf32_rn(outs[row][col4 + 0]), tf32_rn(outs[row][col4 + 1]),
                               tf32_rn(outs[row][col4 + 2]), tf32_rn(outs[row][col4 + 3]));
        float* buf = (row < 32) ? g_A : g_B;
        int cc = row & 31;
        *(float4*)(buf + ((size_t)n * 32 + cc) * 256 + s0 + col4) = v;
    }
}

// ---------------- shared mma.sync tf32 mainloop pieces --------------------------
// loads one 128x32 chunk of a row-major (pitch `gpitch`) matrix into smem buf
__device__ __forceinline__ void load_tile(uint32_t sbase, int smoff_floats,
                                          const float* gbase, int gpitch,
                                          int ko, int t) {
    #pragma unroll
    for (int q = 0; q < 4; q++) {
        int cidx = t + q * 256;
        int row  = cidx >> 3;
        int k4   = cidx & 7;
        uint32_t dst = sbase + (uint32_t)(smoff_floats + row * PITCH + k4 * 4) * 4;
        cp16(dst, gbase + (size_t)row * gpitch + ko + k4 * 4);
    }
}

// compute one 32-wide K chunk: warp (wm,wn), frags in/out acc[4][4][4]
__device__ __forceinline__ void compute_chunk(const float* As, const float* Bs,
                                              int wm, int wn, int g, int c,
                                              float acc[4][4][4]) {
    #pragma unroll
    for (int kk = 0; kk < 4; kk++) {
        int k0 = kk * 8;
        uint32_t af[4][4], bf[4][2];
        #pragma unroll
        for (int mt = 0; mt < 4; mt++) {
            int m0 = wm * 64 + mt * 16;
            af[mt][0] = __float_as_uint(As[(m0 + g)     * PITCH + k0 + c]);
            af[mt][1] = __float_as_uint(As[(m0 + g + 8) * PITCH + k0 + c]);
            af[mt][2] = __float_as_uint(As[(m0 + g)     * PITCH + k0 + c + 4]);
            af[mt][3] = __float_as_uint(As[(m0 + g + 8) * PITCH + k0 + c + 4]);
        }
        #pragma unroll
        for (int nt = 0; nt < 4; nt++) {
            int n0 = wn * 32 + nt * 8;
            bf[nt][0] = __float_as_uint(Bs[(n0 + g) * PITCH + k0 + c]);
            bf[nt][1] = __float_as_uint(Bs[(n0 + g) * PITCH + k0 + c + 4]);
        }
        #pragma unroll
        for (int mt = 0; mt < 4; mt++)
            #pragma unroll
            for (int nt = 0; nt < 4; nt++)
                mma_tf32(acc[mt][nt], af[mt], bf[nt]);
    }
}

// ------------------- K2: G = A * B^T via mma.sync tf32 (8192^2 x 256) ----------
__global__ __launch_bounds__(256, 2) void k2_mma() {
    extern __shared__ float sm[];
    uint32_t sbase = smem_u32(sm);
    const int t = threadIdx.x;
    const int bi = blockIdx.y, bj = blockIdx.x;
    const int wid = t >> 5, lane = t & 31;
    const int wm = wid >> 2, wn = wid & 3;
    const int g = lane >> 2, c = lane & 3;

    float acc[4][4][4];
    #pragma unroll
    for (int a = 0; a < 4; a++)
        #pragma unroll
        for (int b = 0; b < 4; b++)
            #pragma unroll
            for (int r = 0; r < 4; r++) acc[a][b][r] = 0.0f;

    const float* Agm = g_A + (size_t)bi * 128 * 256;
    const float* Bgm = g_B + (size_t)bj * 128 * 256;
    const int B_OFF = 2 * TILE_FLOATS;

    load_tile(sbase, 0, Agm, 256, 0, t);
    load_tile(sbase, B_OFF, Bgm, 256, 0, t);
    CP_COMMIT();

    int buf = 0;
    #pragma unroll 1
    for (int ch = 0; ch < 8; ch++) {
        if (ch + 1 < 8) {
            load_tile(sbase, (buf ^ 1) * TILE_FLOATS, Agm, 256, (ch + 1) * 32, t);
            load_tile(sbase, B_OFF + (buf ^ 1) * TILE_FLOATS, Bgm, 256, (ch + 1) * 32, t);
            CP_COMMIT();
            CP_WAIT1();
        } else {
            CP_WAIT0();
        }
        __syncthreads();
        compute_chunk(sm + buf * TILE_FLOATS, sm + B_OFF + buf * TILE_FLOATS,
                      wm, wn, g, c, acc);
        __syncthreads();
        buf ^= 1;
    }

    // permuted tf32-rounded store: rI=(i*32+cc), cJ=(j*32+e)
    #pragma unroll
    for (int mt = 0; mt < 4; mt++) {
        int rI0 = bi * 128 + wm * 64 + mt * 16;
        #pragma unroll
        for (int half = 0; half < 2; half++) {
            int rI = rI0 + g + half * 8;
            size_t base = ((size_t)(rI >> 5) << 18) + ((size_t)(rI & 31) << 5);
            #pragma unroll
            for (int nt = 0; nt < 4; nt++) {
                int cJ = bj * 128 + wn * 32 + nt * 8 + c * 2;
                float2 v;
                v.x = tf32_rn(acc[mt][nt][half * 2 + 0]);
                v.y = tf32_rn(acc[mt][nt][half * 2 + 1]);
                *(float2*)(g_G + base + ((size_t)(cJ >> 5) << 10) + (cJ & 31)) = v;
            }
        }
    }
}

// ------- K3: out = (G2 @ w_out + b_out)/norm via mma.sync tf32 (65536x128x1024) -
__global__ __launch_bounds__(256, 2) void k3_mma(const float* __restrict__ b_out,
                                                 float* __restrict__ dout) {
    extern __shared__ float sm[];
    uint32_t sbase = smem_u32(sm);
    const int t = threadIdx.x;
    const int bm = blockIdx.x;
    const int wid = t >> 5, lane = t & 31;
    const int wm = wid >> 2, wn = wid & 3;
    const int g = lane >> 2, c = lane & 3;

    float acc[4][4][4];
    #pragma unroll
    for (int a = 0; a < 4; a++)
        #pragma unroll
        for (int b = 0; b < 4; b++)
            #pragma unroll
            for (int r = 0; r < 4; r++) acc[a][b][r] = 0.0f;

    const float* Agm = g_G + (size_t)bm * 128 * 1024;
    const float* Bgm = g_Wt;
    const int B_OFF = 2 * TILE_FLOATS;

    load_tile(sbase, 0, Agm, 1024, 0, t);
    load_tile(sbase, B_OFF, Bgm, 1024, 0, t);
    CP_COMMIT();

    int buf = 0;
    #pragma unroll 1
    for (int ch = 0; ch < 32; ch++) {
        if (ch + 1 < 32) {
            load_tile(sbase, (buf ^ 1) * TILE_FLOATS, Agm, 1024, (ch + 1) * 32, t);
            load_tile(sbase, B_OFF + (buf ^ 1) * TILE_FLOATS, Bgm, 1024, (ch + 1) * 32, t);
            CP_COMMIT();
            CP_WAIT1();
        } else {
            CP_WAIT0();
        }
        __syncthreads();
        compute_chunk(sm + buf * TILE_FLOATS, sm + B_OFF + buf * TILE_FLOATS,
                      wm, wn, g, c, acc);
        __syncthreads();
        buf ^= 1;
    }

    #pragma unroll
    for (int mt = 0; mt < 4; mt++) {
        #pragma unroll
        for (int half = 0; half < 2; half++) {
            int row = bm * 128 + wm * 64 + mt * 16 + g + half * 8;
            float inv = 1.0f / g_norm[row];
            #pragma unroll
            for (int nt = 0; nt < 4; nt++) {
                int col = wn * 32 + nt * 8 + c * 2;
                float2 bo = *(const float2*)(b_out + col);
                float2 v;
                v.x = (acc[mt][nt][half * 2 + 0] + bo.x) * inv;
                v.y = (acc[mt][nt][half * 2 + 1] + bo.y) * inv;
                *(float2*)(dout + (size_t)row * 128 + col) = v;
            }
        }
    }
}

// ----------------------------------- launch -----------------------------------
extern "C" void kernel_launch(void* const* d_in, const int* in_sizes, int n_in,
                              void* d_out, int out_size)
{
    const float* m     = (const float*)d_in[0];
    const float* mask  = (const float*)d_in[1];
    const float* ln_w  = (const float*)d_in[2];
    const float* ln_b  = (const float*)d_in[3];
    const float* w1    = (const float*)d_in[4];
    const float* b1    = (const float*)d_in[5];
    const float* w2    = (const float*)d_in[6];
    const float* b2    = (const float*)d_in[7];
    const float* w_out = (const float*)d_in[8];
    const float* b_out = (const float*)d_in[9];
    float* out = (float*)d_out;

    cudaFuncSetAttribute(k2_mma, cudaFuncAttributeMaxDynamicSharedMemorySize, GEMM_SMEM_BYTES);
    cudaFuncSetAttribute(k3_mma, cudaFuncAttributeMaxDynamicSharedMemorySize, GEMM_SMEM_BYTES);

    k0_stats<<<8192, 256>>>(m);
    k_norm<<<256, 256>>>(mask);
    k_wt<<<dim3(32, 4), 256>>>(w_out);
    k1_proj<<<dim3(256, 8), 256>>>(m, mask, ln_w, ln_b, w1, b1, w2, b2);
    k2_mma<<<dim3(64, 64), 256, GEMM_SMEM_BYTES>>>();
    k3_mma<<<512, 256, GEMM_SMEM_BYTES>>>(b_out, out);
}

// round 4
// speedup vs baseline: 2.6959x; 1.2805x over previous
#include <cuda_runtime.h>
#include <cuda_bf16.h>
#include <cstdint>

// ---------------- scratch (static __device__ -- no allocation) ----------------
__device__ float g_mu[65536];
__device__ float g_rstd[65536];
__device__ float g_A[8192 * 256];      // A[(i*32+c)][s]  tf32-rounded
__device__ float g_B[8192 * 256];      // B[(j*32+e)][s]  tf32-rounded
__device__ float g_G[67108864];        // G2[(i*256+j)*1024 + c*32 + e] tf32-rounded
__device__ float g_norm[65536];
__device__ float g_Wt[128 * 1024];     // Wt[z][k] = tf32(w_out[k][z])
__device__ float g_W12t[64 * 256];     // W'[c64][k] = tf32(lnw[k]*w[k][c]) K-major
__device__ float g_u[64];              // u[c]  = sum_k lnw[k]*w[k][c]
__device__ float g_vb[64];             // vb[c] = sum_k lnb[k]*w[k][c] + bias[c]

#define EPS_MASK 1e-3f
#define LN_EPS   1e-5f

// ------------------------------ helpers ---------------------------------------
__device__ __forceinline__ uint32_t smem_u32(const void* p) {
    uint32_t a;
    asm("{ .reg .u64 t; cvta.to.shared.u64 t, %1; cvt.u32.u64 %0, t; }"
        : "=r"(a) : "l"(p));
    return a;
}
__device__ __forceinline__ float tf32_rn(float x) {
    uint32_t u;
    asm("cvt.rn.tf32.f32 %0, %1;" : "=r"(u) : "f"(x));
    return __uint_as_float(u);
}
__device__ __forceinline__ uint32_t tf32_rn_u(float x) {
    uint32_t u;
    asm("cvt.rn.tf32.f32 %0, %1;" : "=r"(u) : "f"(x));
    return u;
}
__device__ __forceinline__ void cp16(uint32_t saddr, const void* gaddr) {
    asm volatile("cp.async.cg.shared.global [%0], [%1], 16;"
                 :: "r"(saddr), "l"(gaddr) : "memory");
}
#define CP_COMMIT() asm volatile("cp.async.commit_group;" ::: "memory")
#define CP_WAIT0()  asm volatile("cp.async.wait_group 0;" ::: "memory")
#define CP_WAIT1()  asm volatile("cp.async.wait_group 1;" ::: "memory")

__device__ __forceinline__ void mma_tf32(float* d, const uint32_t* a, const uint32_t* b) {
    asm volatile(
        "mma.sync.aligned.m16n8k8.row.col.f32.tf32.tf32.f32 "
        "{%0,%1,%2,%3}, {%4,%5,%6,%7}, {%8,%9}, {%0,%1,%2,%3};"
        : "+f"(d[0]), "+f"(d[1]), "+f"(d[2]), "+f"(d[3])
        : "r"(a[0]), "r"(a[1]), "r"(a[2]), "r"(a[3]), "r"(b[0]), "r"(b[1]));
}

// smem tile geometry: rows x 32 k, pitch 36 floats (conflict-free frags)
#define PITCH 36
#define TILE_FLOATS (128 * PITCH)              // 4608 (128-row tile)
#define GEMM_SMEM_BYTES (4 * TILE_FLOATS * 4)  // A[2] + B[2] = 73728 B

// ------------------------------- K0: LN stats ---------------------------------
__global__ void k0_stats(const float* __restrict__ m) {
    int token = blockIdx.x * 8 + (threadIdx.x >> 5);
    int lane  = threadIdx.x & 31;
    const float4* p = (const float4*)(m + (size_t)token * 256);
    float4 v1 = p[lane];
    float4 v2 = p[lane + 32];
    float s  = v1.x + v1.y + v1.z + v1.w + v2.x + v2.y + v2.z + v2.w;
    float sq = v1.x*v1.x + v1.y*v1.y + v1.z*v1.z + v1.w*v1.w
             + v2.x*v2.x + v2.y*v2.y + v2.z*v2.z + v2.w*v2.w;
    #pragma unroll
    for (int o = 16; o; o >>= 1) {
        s  += __shfl_xor_sync(0xFFFFFFFFu, s,  o);
        sq += __shfl_xor_sync(0xFFFFFFFFu, sq, o);
    }
    if (lane == 0) {
        float mu  = s * (1.0f / 256.0f);
        float var = sq * (1.0f / 256.0f) - mu * mu;
        g_mu[token]   = mu;
        g_rstd[token] = rsqrtf(var + LN_EPS);
    }
}

// ------------------------------ Knorm: mask gram ------------------------------
__global__ void k_norm(const float* __restrict__ mask) {
    int i = blockIdx.x, j = threadIdx.x;
    float acc = EPS_MASK;
    for (int s = 0; s < 256; s++)
        acc += mask[s * 256 + i] * mask[s * 256 + j];
    g_norm[i * 256 + j] = acc;
}

// -------------------- Kwt: tiled transpose + tf32 round of w_out ---------------
__global__ void k_wt(const float* __restrict__ w_out) {
    __shared__ float tile[32][33];
    int kt = blockIdx.x * 32;
    int zt = blockIdx.y * 32;
    int tx = threadIdx.x & 31, ty = threadIdx.x >> 5;
    #pragma unroll
    for (int r = 0; r < 32; r += 8)
        tile[ty + r][tx] = w_out[(size_t)(kt + ty + r) * 128 + zt + tx];
    __syncthreads();
    #pragma unroll
    for (int r = 0; r < 32; r += 8)
        g_Wt[(size_t)(zt + ty + r) * 1024 + kt + tx] = tf32_rn(tile[tx][ty + r]);
}

// ------------- Kw12: fold LN affine into projection weights --------------------
// block c = 0..63 (c<32 -> w1 channel c, else w2 channel c-32); thread k = 0..255
__global__ void k_w12(const float* __restrict__ lnw, const float* __restrict__ lnb,
                      const float* __restrict__ w1, const float* __restrict__ b1,
                      const float* __restrict__ w2, const float* __restrict__ b2) {
    __shared__ float su[256], sv[256];
    int c = blockIdx.x, k = threadIdx.x;
    int cc = (c < 32) ? c : c - 32;
    const float* w = (c < 32) ? w1 : w2;
    float wv = w[(size_t)k * 32 + cc];
    float wp = lnw[k] * wv;
    g_W12t[c * 256 + k] = tf32_rn(wp);
    su[k] = wp;
    sv[k] = lnb[k] * wv;
    __syncthreads();
    for (int o = 128; o; o >>= 1) {
        if (k < o) { su[k] += su[k + o]; sv[k] += sv[k + o]; }
        __syncthreads();
    }
    if (k == 0) {
        g_u[c]  = su[0];
        g_vb[c] = sv[0] + ((c < 32) ? b1[cc] : b2[cc]);
    }
}

// ---------------- generic tile loader (256 threads, ROWS x 32 chunk) -----------
template <int ROWS>
__device__ __forceinline__ void load_tile(uint32_t sbase, int smoff_floats,
                                          const float* gbase, size_t gpitch,
                                          int ko, int t) {
    #pragma unroll
    for (int q = 0; q < (ROWS * 8) / 256; q++) {
        int cidx = t + q * 256;
        int row  = cidx >> 3;
        int k4   = cidx & 7;
        uint32_t dst = sbase + (uint32_t)(smoff_floats + row * PITCH + k4 * 4) * 4;
        cp16(dst, gbase + (size_t)row * gpitch + ko + k4 * 4);
    }
}

// compute one 32-wide K chunk (128x128 tile, 8 warps 2x4, used by k2/k3)
__device__ __forceinline__ void compute_chunk(const float* As, const float* Bs,
                                              int wm, int wn, int g, int c,
                                              float acc[4][4][4]) {
    #pragma unroll
    for (int kk = 0; kk < 4; kk++) {
        int k0 = kk * 8;
        uint32_t af[4][4], bf[4][2];
        #pragma unroll
        for (int mt = 0; mt < 4; mt++) {
            int m0 = wm * 64 + mt * 16;
            af[mt][0] = __float_as_uint(As[(m0 + g)     * PITCH + k0 + c]);
            af[mt][1] = __float_as_uint(As[(m0 + g + 8) * PITCH + k0 + c]);
            af[mt][2] = __float_as_uint(As[(m0 + g)     * PITCH + k0 + c + 4]);
            af[mt][3] = __float_as_uint(As[(m0 + g + 8) * PITCH + k0 + c + 4]);
        }
        #pragma unroll
        for (int nt = 0; nt < 4; nt++) {
            int n0 = wn * 32 + nt * 8;
            bf[nt][0] = __float_as_uint(Bs[(n0 + g) * PITCH + k0 + c]);
            bf[nt][1] = __float_as_uint(Bs[(n0 + g) * PITCH + k0 + c + 4]);
        }
        #pragma unroll
        for (int mt = 0; mt < 4; mt++)
            #pragma unroll
            for (int nt = 0; nt < 4; nt++)
                mma_tf32(acc[mt][nt], af[mt], bf[nt]);
    }
}

// --------- K1: fused LN+proj as GEMM  raw_m[128s x 256k] @ W'[256k x 64c] ------
// grid 512: n = bx>>1, s0 = (bx&1)*128. 8 warps: wm=wid>>2 (2), wn=wid&3 (4).
#define K1_ATILE (128 * PITCH)
#define K1_BTILE (64 * PITCH)
#define K1_SMEM_BYTES ((2 * K1_ATILE + 2 * K1_BTILE) * 4)
__global__ __launch_bounds__(256) void k1_mma(const float* __restrict__ m,
                                              const float* __restrict__ mask) {
    extern __shared__ float sm[];
    uint32_t sbase = smem_u32(sm);
    const int t = threadIdx.x;
    const int n  = blockIdx.x >> 1;
    const int s0 = (blockIdx.x & 1) * 128;
    const int wid = t >> 5, lane = t & 31;
    const int wm = wid >> 2, wn = wid & 3;
    const int g = lane >> 2, c = lane & 3;

    float acc[4][2][4];
    #pragma unroll
    for (int a = 0; a < 4; a++)
        #pragma unroll
        for (int b = 0; b < 2; b++)
            #pragma unroll
            for (int r = 0; r < 4; r++) acc[a][b][r] = 0.0f;

    const float* Agm = m + ((size_t)s0 * 256 + n) * 256;  // row stride 65536 floats
    const int B_OFF = 2 * K1_ATILE;

    load_tile<128>(sbase, 0, Agm, 65536, 0, t);
    load_tile<64>(sbase, B_OFF, g_W12t, 256, 0, t);
    CP_COMMIT();

    int buf = 0;
    #pragma unroll 1
    for (int ch = 0; ch < 8; ch++) {
        if (ch + 1 < 8) {
            load_tile<128>(sbase, (buf ^ 1) * K1_ATILE, Agm, 65536, (ch + 1) * 32, t);
            load_tile<64>(sbase, B_OFF + (buf ^ 1) * K1_BTILE, g_W12t, 256, (ch + 1) * 32, t);
            CP_COMMIT();
            CP_WAIT1();
        } else {
            CP_WAIT0();
        }
        __syncthreads();
        const float* As = sm + buf * K1_ATILE;
        const float* Bs = sm + B_OFF + buf * K1_BTILE;
        #pragma unroll
        for (int kk = 0; kk < 4; kk++) {
            int k0 = kk * 8;
            uint32_t af[4][4], bf[2][2];
            #pragma unroll
            for (int mt = 0; mt < 4; mt++) {
                int m0 = wm * 64 + mt * 16;
                af[mt][0] = tf32_rn_u(As[(m0 + g)     * PITCH + k0 + c]);
                af[mt][1] = tf32_rn_u(As[(m0 + g + 8) * PITCH + k0 + c]);
                af[mt][2] = tf32_rn_u(As[(m0 + g)     * PITCH + k0 + c + 4]);
                af[mt][3] = tf32_rn_u(As[(m0 + g + 8) * PITCH + k0 + c + 4]);
            }
            #pragma unroll
            for (int nt = 0; nt < 2; nt++) {
                int n0 = wn * 16 + nt * 8;
                bf[nt][0] = __float_as_uint(Bs[(n0 + g) * PITCH + k0 + c]);
                bf[nt][1] = __float_as_uint(Bs[(n0 + g) * PITCH + k0 + c + 4]);
            }
            #pragma unroll
            for (int mt = 0; mt < 4; mt++)
                #pragma unroll
                for (int nt = 0; nt < 2; nt++)
                    mma_tf32(acc[mt][nt], af[mt], bf[nt]);
        }
        __syncthreads();
        buf ^= 1;
    }

    // epilogue: val = (rstd*acc - mu*rstd*u[ch] + vb[ch]) * mask ; transposed store
    #pragma unroll
    for (int mt = 0; mt < 4; mt++) {
        #pragma unroll
        for (int half = 0; half < 2; half++) {
            int s = s0 + wm * 64 + mt * 16 + g + half * 8;
            int tok = s * 256 + n;
            float mu = g_mu[tok], rs = g_rstd[tok];
            float murs = -mu * rs;
            float mval = mask[tok];
            #pragma unroll
            for (int nt = 0; nt < 2; nt++) {
                #pragma unroll
                for (int x = 0; x < 2; x++) {
                    int ch = wn * 16 + nt * 8 + c * 2 + x;
                    float val = (rs * acc[mt][nt][half * 2 + x]
                                 + murs * g_u[ch] + g_vb[ch]) * mval;
                    float* buf_out = (ch < 32) ? g_A : g_B;
                    int cc = ch & 31;
                    buf_out[((size_t)n * 32 + cc) * 256 + s] = tf32_rn(val);
                }
            }
        }
    }
}

// ------------------- K2: G = A * B^T via mma.sync tf32 (8192^2 x 256) ----------
__global__ __launch_bounds__(256, 2) void k2_mma() {
    extern __shared__ float sm[];
    uint32_t sbase = smem_u32(sm);
    const int t = threadIdx.x;
    const int bi = blockIdx.y, bj = blockIdx.x;
    const int wid = t >> 5, lane = t & 31;
    const int wm = wid >> 2, wn = wid & 3;
    const int g = lane >> 2, c = lane & 3;

    float acc[4][4][4];
    #pragma unroll
    for (int a = 0; a < 4; a++)
        #pragma unroll
        for (int b = 0; b < 4; b++)
            #pragma unroll
            for (int r = 0; r < 4; r++) acc[a][b][r] = 0.0f;

    const float* Agm = g_A + (size_t)bi * 128 * 256;
    const float* Bgm = g_B + (size_t)bj * 128 * 256;
    const int B_OFF = 2 * TILE_FLOATS;

    load_tile<128>(sbase, 0, Agm, 256, 0, t);
    load_tile<128>(sbase, B_OFF, Bgm, 256, 0, t);
    CP_COMMIT();

    int buf = 0;
    #pragma unroll 1
    for (int ch = 0; ch < 8; ch++) {
        if (ch + 1 < 8) {
            load_tile<128>(sbase, (buf ^ 1) * TILE_FLOATS, Agm, 256, (ch + 1) * 32, t);
            load_tile<128>(sbase, B_OFF + (buf ^ 1) * TILE_FLOATS, Bgm, 256, (ch + 1) * 32, t);
            CP_COMMIT();
            CP_WAIT1();
        } else {
            CP_WAIT0();
        }
        __syncthreads();
        compute_chunk(sm + buf * TILE_FLOATS, sm + B_OFF + buf * TILE_FLOATS,
                      wm, wn, g, c, acc);
        __syncthreads();
        buf ^= 1;
    }

    #pragma unroll
    for (int mt = 0; mt < 4; mt++) {
        int rI0 = bi * 128 + wm * 64 + mt * 16;
        #pragma unroll
        for (int half = 0; half < 2; half++) {
            int rI = rI0 + g + half * 8;
            size_t base = ((size_t)(rI >> 5) << 18) + ((size_t)(rI & 31) << 5);
            #pragma unroll
            for (int nt = 0; nt < 4; nt++) {
                int cJ = bj * 128 + wn * 32 + nt * 8 + c * 2;
                float2 v;
                v.x = tf32_rn(acc[mt][nt][half * 2 + 0]);
                v.y = tf32_rn(acc[mt][nt][half * 2 + 1]);
                *(float2*)(g_G + base + ((size_t)(cJ >> 5) << 10) + (cJ & 31)) = v;
            }
        }
    }
}

// ------- K3: out = (G2 @ w_out + b_out)/norm via mma.sync tf32 (65536x128x1024) -
__global__ __launch_bounds__(256, 2) void k3_mma(const float* __restrict__ b_out,
                                                 float* __restrict__ dout) {
    extern __shared__ float sm[];
    uint32_t sbase = smem_u32(sm);
    const int t = threadIdx.x;
    const int bm = blockIdx.x;
    const int wid = t >> 5, lane = t & 31;
    const int wm = wid >> 2, wn = wid & 3;
    const int g = lane >> 2, c = lane & 3;

    float acc[4][4][4];
    #pragma unroll
    for (int a = 0; a < 4; a++)
        #pragma unroll
        for (int b = 0; b < 4; b++)
            #pragma unroll
            for (int r = 0; r < 4; r++) acc[a][b][r] = 0.0f;

    const float* Agm = g_G + (size_t)bm * 128 * 1024;
    const float* Bgm = g_Wt;
    const int B_OFF = 2 * TILE_FLOATS;

    load_tile<128>(sbase, 0, Agm, 1024, 0, t);
    load_tile<128>(sbase, B_OFF, Bgm, 1024, 0, t);
    CP_COMMIT();

    int buf = 0;
    #pragma unroll 1
    for (int ch = 0; ch < 32; ch++) {
        if (ch + 1 < 32) {
            load_tile<128>(sbase, (buf ^ 1) * TILE_FLOATS, Agm, 1024, (ch + 1) * 32, t);
            load_tile<128>(sbase, B_OFF + (buf ^ 1) * TILE_FLOATS, Bgm, 1024, (ch + 1) * 32, t);
            CP_COMMIT();
            CP_WAIT1();
        } else {
            CP_WAIT0();
        }
        __syncthreads();
        compute_chunk(sm + buf * TILE_FLOATS, sm + B_OFF + buf * TILE_FLOATS,
                      wm, wn, g, c, acc);
        __syncthreads();
        buf ^= 1;
    }

    #pragma unroll
    for (int mt = 0; mt < 4; mt++) {
        #pragma unroll
        for (int half = 0; half < 2; half++) {
            int row = bm * 128 + wm * 64 + mt * 16 + g + half * 8;
            float inv = 1.0f / g_norm[row];
            #pragma unroll
            for (int nt = 0; nt < 4; nt++) {
                int col = wn * 32 + nt * 8 + c * 2;
                float2 bo = *(const float2*)(b_out + col);
                float2 v;
                v.x = (acc[mt][nt][half * 2 + 0] + bo.x) * inv;
                v.y = (acc[mt][nt][half * 2 + 1] + bo.y) * inv;
                *(float2*)(dout + (size_t)row * 128 + col) = v;
            }
        }
    }
}

// ----------------------------------- launch -----------------------------------
extern "C" void kernel_launch(void* const* d_in, const int* in_sizes, int n_in,
                              void* d_out, int out_size)
{
    const float* m     = (const float*)d_in[0];
    const float* mask  = (const float*)d_in[1];
    const float* ln_w  = (const float*)d_in[2];
    const float* ln_b  = (const float*)d_in[3];
    const float* w1    = (const float*)d_in[4];
    const float* b1    = (const float*)d_in[5];
    const float* w2    = (const float*)d_in[6];
    const float* b2    = (const float*)d_in[7];
    const float* w_out = (const float*)d_in[8];
    const float* b_out = (const float*)d_in[9];
    float* out = (float*)d_out;

    cudaFuncSetAttribute(k1_mma, cudaFuncAttributeMaxDynamicSharedMemorySize, K1_SMEM_BYTES);
    cudaFuncSetAttribute(k2_mma, cudaFuncAttributeMaxDynamicSharedMemorySize, GEMM_SMEM_BYTES);
    cudaFuncSetAttribute(k3_mma, cudaFuncAttributeMaxDynamicSharedMemorySize, GEMM_SMEM_BYTES);

    k0_stats<<<8192, 256>>>(m);
    k_norm<<<256, 256>>>(mask);
    k_wt<<<dim3(32, 4), 256>>>(w_out);
    k_w12<<<64, 256>>>(ln_w, ln_b, w1, b1, w2, b2);
    k1_mma<<<512, 256, K1_SMEM_BYTES>>>(m, mask);
    k2_mma<<<dim3(64, 64), 256, GEMM_SMEM_BYTES>>>();
    k3_mma<<<512, 256, GEMM_SMEM_BYTES>>>(b_out, out);
}